// round 5
// baseline (speedup 1.0000x reference)
#include <cuda_runtime.h>
#include <math.h>

#define B_  32
#define L_  4096
#define D_  1024
#define D4_ (D_ / 4)           // 256 float4 per row
#define NA_ 8
#define NCHUNK 16
#define LCHUNK (L_ / NCHUNK)   // 256
#define NW_ 8                  // warps per accum block

// Partial sums per (b, l-chunk, action, d). 16.8 MB scratch.
__device__ float g_part[B_ * NCHUNK * NA_ * D_];
// Per (b, l-chunk, action) masked counts.
__device__ int   g_cnt [B_ * NCHUNK * NA_];

// ---------------------------------------------------------------------------
// Kernel 1: masked segmented sum into per-chunk partials.
// grid = (NCHUNK, B), 256 threads; thread owns one float4 column (d4 = tid).
// Rows are stably partitioned by action with warp ballots, then the main loop
// is branchless (one accumulator per group) with 4 loads in flight.
// ---------------------------------------------------------------------------
__global__ __launch_bounds__(256, 6)
void accum_kernel(const float4* __restrict__ emb4,
                  const int* __restrict__ actions,
                  const int* __restrict__ mask)
{
    const int chunk = blockIdx.x;
    const int b     = blockIdx.y;
    const int tid   = threadIdx.x;
    const int l0    = chunk * LCHUNK;
    const int w     = tid >> 5, lane = tid & 31;

    __shared__ short s_order[LCHUNK];
    __shared__ int   s_wcnt[NA_ * NW_];
    __shared__ int   s_woff[NA_ * NW_ + 1];

    // mask is bool upcast to a 4-byte type by the harness; nonzero = True.
    int act;
    {
        int a = actions[b * L_ + l0 + tid];
        int m = mask[b * L_ + l0 + tid];
        act = (m != 0) ? a : -1;
    }

    // Stable partition by action: warp ballots + popc ranks.
    const unsigned lt = (1u << lane) - 1u;
    int myrank = 0;
    #pragma unroll
    for (int aa = 0; aa < NA_; ++aa) {
        unsigned bal = __ballot_sync(0xffffffffu, act == aa);
        if (lane == 0) s_wcnt[aa * NW_ + w] = __popc(bal);
        if (act == aa) myrank = __popc(bal & lt);
    }
    __syncthreads();
    if (tid == 0) {
        int acc = 0;
        #pragma unroll
        for (int q = 0; q < NA_ * NW_; ++q) { s_woff[q] = acc; acc += s_wcnt[q]; }
        s_woff[NA_ * NW_] = acc;
    }
    __syncthreads();
    if (act >= 0) s_order[s_woff[act * NW_ + w] + myrank] = (short)tid;
    if (tid < NA_)
        g_cnt[(b * NCHUNK + chunk) * NA_ + tid] =
            s_woff[(tid + 1) * NW_] - s_woff[tid * NW_];
    __syncthreads();

    const float4* base = emb4 + ((size_t)b * L_ + l0) * D4_ + tid;
    float4* outp = reinterpret_cast<float4*>(g_part)
                   + (size_t)(b * NCHUNK + chunk) * NA_ * D4_ + tid;

    #pragma unroll 1
    for (int a = 0; a < NA_; ++a) {
        float4 acc = make_float4(0.f, 0.f, 0.f, 0.f);
        const int s = s_woff[a * NW_], e = s_woff[(a + 1) * NW_];
        int i = s;
        for (; i + 4 <= e; i += 4) {
            const float4 v0 = base[(int)s_order[i]     * D4_];
            const float4 v1 = base[(int)s_order[i + 1] * D4_];
            const float4 v2 = base[(int)s_order[i + 2] * D4_];
            const float4 v3 = base[(int)s_order[i + 3] * D4_];
            acc.x += (v0.x + v1.x) + (v2.x + v3.x);
            acc.y += (v0.y + v1.y) + (v2.y + v3.y);
            acc.z += (v0.z + v1.z) + (v2.z + v3.z);
            acc.w += (v0.w + v1.w) + (v2.w + v3.w);
        }
        for (; i < e; ++i) {
            const float4 v = base[(int)s_order[i] * D4_];
            acc.x += v.x; acc.y += v.y; acc.z += v.z; acc.w += v.w;
        }
        outp[a * D4_] = acc;
    }
}

// ---------------------------------------------------------------------------
// Kernel 2 (fused head): one block per batch b computes feats for ALL 8
// actions in smem, then both MLPs (weight loads amortized across actions),
// softmax/sigmoid, and all 6 outputs. grid = 32, block = 512.
// ---------------------------------------------------------------------------
__global__ __launch_bounds__(512)
void head_kernel(const float* __restrict__ sw1, const float* __restrict__ sb1,
                 const float* __restrict__ sw2, const float* __restrict__ sb2,
                 const float* __restrict__ ew1, const float* __restrict__ eb1,
                 const float* __restrict__ ew2, const float* __restrict__ eb2,
                 float* __restrict__ out)
{
    const int b   = blockIdx.x;
    const int tid = threadIdx.x;

    __shared__ float s_feat[NA_ * D_];      // 32 KB
    __shared__ float s_h1[NA_ * 128];
    __shared__ float s_eh[NA_ * 64];
    __shared__ float s_logit[NA_ * 14];
    __shared__ float s_eff[NA_ * 3];
    __shared__ float s_inv[NA_], s_seen[NA_];

    // ---- counts ----
    if (tid < NA_) {
        int c = 0;
        #pragma unroll
        for (int ch = 0; ch < NCHUNK; ++ch)
            c += g_cnt[(b * NCHUNK + ch) * NA_ + tid];
        s_inv[tid]  = 1.0f / fmaxf((float)c, 1.0f);
        s_seen[tid] = (c > 0) ? 1.0f : 0.0f;
    }

    // ---- feats for all 8 actions: 2048 float4 columns, 4 per thread ----
    const float4* gp4 = reinterpret_cast<const float4*>(g_part)
                        + (size_t)b * NCHUNK * NA_ * D4_;
    float4 acc[4];
    #pragma unroll
    for (int k = 0; k < 4; ++k) {
        const int col = tid + k * 512;      // col = a*256 + d4
        float4 s = make_float4(0.f, 0.f, 0.f, 0.f);
        #pragma unroll
        for (int ch = 0; ch < NCHUNK; ++ch) {
            const float4 v = gp4[(size_t)ch * NA_ * D4_ + col];
            s.x += v.x; s.y += v.y; s.z += v.z; s.w += v.w;
        }
        acc[k] = s;
    }
    __syncthreads();                        // s_inv ready
    float4* s_feat4 = reinterpret_cast<float4*>(s_feat);
    #pragma unroll
    for (int k = 0; k < 4; ++k) {
        const int col = tid + k * 512;
        const float inv = s_inv[col >> 8];
        acc[k].x *= inv; acc[k].y *= inv; acc[k].z *= inv; acc[k].w *= inv;
        s_feat4[col] = acc[k];
    }
    __syncthreads();

    // ---- MLP1 layer 1: 8a x 128n outputs; thread does (a0, n) and (a0+4, n),
    //      sharing each sw1 load between the two actions ----
    {
        const int n = tid & 127, a0 = tid >> 7;   // a0 in 0..3
        const float* f0 = s_feat + a0 * D_;
        const float* f1 = s_feat + (a0 + 4) * D_;
        float acc0 = 0.f, acc1 = 0.f;
        #pragma unroll 8
        for (int d = 0; d < D_; ++d) {
            const float wv = sw1[d * 128 + n];
            acc0 = fmaf(f0[d], wv, acc0);
            acc1 = fmaf(f1[d], wv, acc1);
        }
        const float bias = sb1[n];
        s_h1[a0 * 128 + n]       = fmaxf(acc0 + bias, 0.0f);
        s_h1[(a0 + 4) * 128 + n] = fmaxf(acc1 + bias, 0.0f);
    }

    // ---- effect MLP layer 1: 8a x 64n outputs, one per thread ----
    {
        const int n = tid & 63, a = tid >> 6;     // a in 0..7
        const float* f = s_feat + a * D_;
        float acc2 = 0.f;
        #pragma unroll 8
        for (int d = 0; d < D_; ++d)
            acc2 = fmaf(f[d], ew1[d * 64 + n], acc2);
        s_eh[a * 64 + n] = fmaxf(acc2 + eb1[n], 0.0f);
    }
    __syncthreads();

    // ---- layer 2 ----
    if (tid < NA_ * 14) {                         // shift logits: 112 outputs
        const int a = tid / 14, o = tid % 14;
        const float* h = s_h1 + a * 128;
        float acc3 = sb2[o];
        #pragma unroll 8
        for (int k = 0; k < 128; ++k)
            acc3 = fmaf(h[k], sw2[k * 14 + o], acc3);
        s_logit[tid] = acc3;
    } else if (tid >= 128 && tid < 128 + NA_ * 3) { // effects: 24 outputs
        const int idx = tid - 128, a = idx / 3, j = idx % 3;
        const float* h = s_eh + a * 64;
        float acc4 = eb2[j];
        #pragma unroll 8
        for (int k = 0; k < 64; ++k)
            acc4 = fmaf(h[k], ew2[k * 3 + j], acc4);
        s_eff[idx] = acc4;
    }
    __syncthreads();

    // Output layout (flat float32, reference tuple order):
    //   [0,512)     shift (B,8,2)   [512,2304)  dx_logits (B,8,7)
    //   [2304,4096) dy_logits       [4096,4352) sig(e0)*seen
    //   [4352,4608) sig(e1)*seen    [4608,4864) e2*seen
    if (tid < NA_ * 14) {                         // raw logits out
        const int a = tid / 14, o = tid % 14;
        const int ba = b * NA_ + a;
        if (o < 7) out[512  + ba * 7 + o]       = s_logit[tid];
        else       out[2304 + ba * 7 + (o - 7)] = s_logit[tid];
    }

    if (tid < NA_) {
        const int a  = tid;
        const int ba = b * NA_ + a;
        const float seen = s_seen[a];
        const float bins[7] = {-16.f, -8.f, -4.f, 0.f, 4.f, 8.f, 16.f};
        #pragma unroll
        for (int h = 0; h < 2; ++h) {
            const float* lg = &s_logit[a * 14 + h * 7];
            float mx = lg[0];
            #pragma unroll
            for (int j = 1; j < 7; ++j) mx = fmaxf(mx, lg[j]);
            float den = 0.f, num = 0.f;
            #pragma unroll
            for (int j = 0; j < 7; ++j) {
                const float e = __expf(lg[j] - mx);
                den += e;
                num += e * bins[j];
            }
            out[ba * 2 + h] = (num / den) * seen;
        }
        out[4096 + ba] = (1.0f / (1.0f + __expf(-s_eff[a * 3 + 0]))) * seen;
        out[4352 + ba] = (1.0f / (1.0f + __expf(-s_eff[a * 3 + 1]))) * seen;
        out[4608 + ba] = s_eff[a * 3 + 2] * seen;
    }
}

// ---------------------------------------------------------------------------
extern "C" void kernel_launch(void* const* d_in, const int* in_sizes, int n_in,
                              void* d_out, int out_size)
{
    const float4* emb4 = (const float4*)d_in[0];
    const int*    act  = (const int*)d_in[1];
    const int*    mask = (const int*)d_in[2];
    const float* sw1 = (const float*)d_in[3];
    const float* sb1 = (const float*)d_in[4];
    const float* sw2 = (const float*)d_in[5];
    const float* sb2 = (const float*)d_in[6];
    const float* ew1 = (const float*)d_in[7];
    const float* eb1 = (const float*)d_in[8];
    const float* ew2 = (const float*)d_in[9];
    const float* eb2 = (const float*)d_in[10];
    float* out = (float*)d_out;

    accum_kernel<<<dim3(NCHUNK, B_), 256>>>(emb4, act, mask);
    head_kernel<<<B_, 512>>>(sw1, sb1, sw2, sb2, ew1, eb1, ew2, eb2, out);
}

// round 6
// speedup vs baseline: 1.8908x; 1.8908x over previous
#include <cuda_runtime.h>
#include <math.h>

#define B_  32
#define L_  4096
#define D_  1024
#define D4_ (D_ / 4)           // 256 float4 per row
#define NA_ 8
#define NCHUNK 16
#define LCHUNK (L_ / NCHUNK)   // 256
#define NW_ 8                  // warps per accum block

// Partial sums per (b, l-chunk, action, d). 16.8 MB scratch (L2-resident).
__device__ float g_part[B_ * NCHUNK * NA_ * D_];
// Per (b, l-chunk, action) masked counts.
__device__ int   g_cnt [B_ * NCHUNK * NA_];

// ---------------------------------------------------------------------------
// Kernel 1: masked segmented sum into per-chunk partials.
// grid = (NCHUNK, B), 256 threads; thread owns one float4 column (d4 = tid).
// Rows are stably partitioned by action with warp ballots, then the main loop
// is branchless (one accumulator per group) with 4 loads in flight.
// (Measured ~85 us in R4/R5 — keep unchanged.)
// ---------------------------------------------------------------------------
__global__ __launch_bounds__(256, 6)
void accum_kernel(const float4* __restrict__ emb4,
                  const int* __restrict__ actions,
                  const int* __restrict__ mask)
{
    const int chunk = blockIdx.x;
    const int b     = blockIdx.y;
    const int tid   = threadIdx.x;
    const int l0    = chunk * LCHUNK;
    const int w     = tid >> 5, lane = tid & 31;

    __shared__ short s_order[LCHUNK];
    __shared__ int   s_wcnt[NA_ * NW_];
    __shared__ int   s_woff[NA_ * NW_ + 1];

    // mask is bool upcast to a 4-byte type by the harness; nonzero = True.
    int act;
    {
        int a = actions[b * L_ + l0 + tid];
        int m = mask[b * L_ + l0 + tid];
        act = (m != 0) ? a : -1;
    }

    // Stable partition by action: warp ballots + popc ranks.
    const unsigned lt = (1u << lane) - 1u;
    int myrank = 0;
    #pragma unroll
    for (int aa = 0; aa < NA_; ++aa) {
        unsigned bal = __ballot_sync(0xffffffffu, act == aa);
        if (lane == 0) s_wcnt[aa * NW_ + w] = __popc(bal);
        if (act == aa) myrank = __popc(bal & lt);
    }
    __syncthreads();
    if (tid == 0) {
        int acc = 0;
        #pragma unroll
        for (int q = 0; q < NA_ * NW_; ++q) { s_woff[q] = acc; acc += s_wcnt[q]; }
        s_woff[NA_ * NW_] = acc;
    }
    __syncthreads();
    if (act >= 0) s_order[s_woff[act * NW_ + w] + myrank] = (short)tid;
    if (tid < NA_)
        g_cnt[(b * NCHUNK + chunk) * NA_ + tid] =
            s_woff[(tid + 1) * NW_] - s_woff[tid * NW_];
    __syncthreads();

    const float4* base = emb4 + ((size_t)b * L_ + l0) * D4_ + tid;
    float4* outp = reinterpret_cast<float4*>(g_part)
                   + (size_t)(b * NCHUNK + chunk) * NA_ * D4_ + tid;

    #pragma unroll 1
    for (int a = 0; a < NA_; ++a) {
        float4 acc = make_float4(0.f, 0.f, 0.f, 0.f);
        const int s = s_woff[a * NW_], e = s_woff[(a + 1) * NW_];
        int i = s;
        for (; i + 4 <= e; i += 4) {
            const float4 v0 = base[(int)s_order[i]     * D4_];
            const float4 v1 = base[(int)s_order[i + 1] * D4_];
            const float4 v2 = base[(int)s_order[i + 2] * D4_];
            const float4 v3 = base[(int)s_order[i + 3] * D4_];
            acc.x += (v0.x + v1.x) + (v2.x + v3.x);
            acc.y += (v0.y + v1.y) + (v2.y + v3.y);
            acc.z += (v0.z + v1.z) + (v2.z + v3.z);
            acc.w += (v0.w + v1.w) + (v2.w + v3.w);
        }
        for (; i < e; ++i) {
            const float4 v = base[(int)s_order[i] * D4_];
            acc.x += v.x; acc.y += v.y; acc.z += v.z; acc.w += v.w;
        }
        outp[a * D4_] = acc;
    }
}

// ---------------------------------------------------------------------------
// Kernel 2: reduce partials -> feats, both MLPs, softmax, sigmoid, outputs.
// grid = (NA, B) = 256 blocks, 512 threads (R3 structure — parallelism over
// traffic), with dual accumulator chains in the layer-1 loops for ILP.
// ---------------------------------------------------------------------------
__global__ __launch_bounds__(512)
void head_kernel(const float* __restrict__ sw1, const float* __restrict__ sb1,
                 const float* __restrict__ sw2, const float* __restrict__ sb2,
                 const float* __restrict__ ew1, const float* __restrict__ eb1,
                 const float* __restrict__ ew2, const float* __restrict__ eb2,
                 float* __restrict__ out)
{
    const int a   = blockIdx.x;
    const int b   = blockIdx.y;
    const int tid = threadIdx.x;

    __shared__ float s_feat[D_];
    __shared__ float s_part[512];
    __shared__ float s_h1[128];
    __shared__ float s_eh[64];
    __shared__ float s_logit[14];
    __shared__ float s_eff[3];
    __shared__ float s_scal[2];   // [0] = inv_cnt, [1] = seen

    // ---- counts (from g_cnt) ----
    if (tid == 0) {
        int c = 0;
        #pragma unroll
        for (int ch = 0; ch < NCHUNK; ++ch)
            c += g_cnt[(b * NCHUNK + ch) * NA_ + a];
        s_scal[0] = 1.0f / fmaxf((float)c, 1.0f);
        s_scal[1] = (c > 0) ? 1.0f : 0.0f;
    }

    // ---- feats: each thread reduces 2 d-columns over 16 chunk partials ----
    float f0 = 0.f, f1 = 0.f;
    const float* gp = g_part + ((size_t)b * NCHUNK * NA_ + a) * D_;
    #pragma unroll
    for (int ch = 0; ch < NCHUNK; ++ch) {
        f0 += gp[(size_t)ch * NA_ * D_ + tid];
        f1 += gp[(size_t)ch * NA_ * D_ + tid + 512];
    }
    __syncthreads();           // s_scal ready
    const float inv_cnt = s_scal[0];
    const float seen    = s_scal[1];
    s_feat[tid]       = f0 * inv_cnt;
    s_feat[tid + 512] = f1 * inv_cnt;
    __syncthreads();

    // ---- MLP1 layer 1: 128 neurons, 4 threads each; dual acc chains ----
    {
        const int n = tid & 127, g = tid >> 7;      // g in 0..3
        float accA = 0.f, accB = 0.f;
        #pragma unroll 4
        for (int i = 0; i < 256; i += 2) {
            const int d = g * 256 + i;
            accA = fmaf(s_feat[d],     sw1[d * 128 + n],       accA);
            accB = fmaf(s_feat[d + 1], sw1[(d + 1) * 128 + n], accB);
        }
        s_part[tid] = accA + accB;
    }
    __syncthreads();
    if (tid < 128) {
        float v = (s_part[tid] + s_part[128 + tid])
                + (s_part[256 + tid] + s_part[384 + tid]);
        s_h1[tid] = fmaxf(v + sb1[tid], 0.0f);
    }
    __syncthreads();

    // ---- effect MLP layer 1: 64 neurons, 8 threads each; dual acc chains ----
    {
        const int n = tid & 63, g = tid >> 6;       // g in 0..7
        float accA = 0.f, accB = 0.f;
        #pragma unroll 4
        for (int i = 0; i < 128; i += 2) {
            const int d = g * 128 + i;
            accA = fmaf(s_feat[d],     ew1[d * 64 + n],       accA);
            accB = fmaf(s_feat[d + 1], ew1[(d + 1) * 64 + n], accB);
        }
        s_part[tid] = accA + accB;
    }
    __syncthreads();
    if (tid < 64) {
        float v = 0.f;
        #pragma unroll
        for (int g = 0; g < 8; ++g) v += s_part[g * 64 + tid];
        s_eh[tid] = fmaxf(v + eb1[tid], 0.0f);
    }
    __syncthreads();

    // ---- layer 2: warp-per-output ----
    {
        const int w = tid >> 5, lane = tid & 31;
        if (w < 14) {
            float acc = 0.f;
            #pragma unroll
            for (int k = lane; k < 128; k += 32)
                acc = fmaf(s_h1[k], sw2[k * 14 + w], acc);
            #pragma unroll
            for (int off = 16; off > 0; off >>= 1)
                acc += __shfl_down_sync(0xffffffffu, acc, off);
            if (lane == 0) s_logit[w] = acc + sb2[w];
        } else if (w == 14) {
            #pragma unroll
            for (int j = 0; j < 3; ++j) {
                float acc = fmaf(s_eh[lane], ew2[lane * 3 + j],
                                 s_eh[lane + 32] * ew2[(lane + 32) * 3 + j]);
                #pragma unroll
                for (int off = 16; off > 0; off >>= 1)
                    acc += __shfl_down_sync(0xffffffffu, acc, off);
                if (lane == 0) s_eff[j] = acc + eb2[j];
            }
        }
    }
    __syncthreads();

    // Output layout (flat float32, reference tuple order):
    //   [0,512)     shift (B,8,2)   [512,2304)  dx_logits (B,8,7)
    //   [2304,4096) dy_logits       [4096,4352) sig(e0)*seen
    //   [4352,4608) sig(e1)*seen    [4608,4864) e2*seen
    const int ba = b * NA_ + a;

    if (tid < 7)              out[512  + ba * 7 + tid]       = s_logit[tid];
    if (tid >= 7 && tid < 14) out[2304 + ba * 7 + (tid - 7)] = s_logit[tid];

    if (tid == 0) {
        const float bins[7] = {-16.f, -8.f, -4.f, 0.f, 4.f, 8.f, 16.f};
        #pragma unroll
        for (int h = 0; h < 2; ++h) {
            const float* lg = &s_logit[h * 7];
            float mx = lg[0];
            #pragma unroll
            for (int j = 1; j < 7; ++j) mx = fmaxf(mx, lg[j]);
            float den = 0.f, num = 0.f;
            #pragma unroll
            for (int j = 0; j < 7; ++j) {
                const float e = __expf(lg[j] - mx);
                den += e;
                num += e * bins[j];
            }
            out[ba * 2 + h] = (num / den) * seen;
        }
        out[4096 + ba] = (1.0f / (1.0f + __expf(-s_eff[0]))) * seen;
        out[4352 + ba] = (1.0f / (1.0f + __expf(-s_eff[1]))) * seen;
        out[4608 + ba] = s_eff[2] * seen;
    }
}

// ---------------------------------------------------------------------------
extern "C" void kernel_launch(void* const* d_in, const int* in_sizes, int n_in,
                              void* d_out, int out_size)
{
    const float4* emb4 = (const float4*)d_in[0];
    const int*    act  = (const int*)d_in[1];
    const int*    mask = (const int*)d_in[2];
    const float* sw1 = (const float*)d_in[3];
    const float* sb1 = (const float*)d_in[4];
    const float* sw2 = (const float*)d_in[5];
    const float* sb2 = (const float*)d_in[6];
    const float* ew1 = (const float*)d_in[7];
    const float* eb1 = (const float*)d_in[8];
    const float* ew2 = (const float*)d_in[9];
    const float* eb2 = (const float*)d_in[10];
    float* out = (float*)d_out;

    accum_kernel<<<dim3(NCHUNK, B_), 256>>>(emb4, act, mask);
    head_kernel<<<dim3(NA_, B_), 512>>>(sw1, sb1, sw2, sb2,
                                        ew1, eb1, ew2, eb2, out);
}